// round 1
// baseline (speedup 1.0000x reference)
#include <cuda_runtime.h>
#include <math.h>

#define BSZ    8
#define NTOK   1024
#define DMODEL 512
#define QKV3   1536
#define NH     8
#define DHE    64
#define DINNER 512
#define ASCALE 0.125f

// ---------------- scratch (device globals; no runtime allocation) ----------
__device__ float  g_qkv[BSZ * NTOK * QKV3];    // 48 MB  [b*N + n][1536]
__device__ float  g_attn[BSZ * NTOK * DINNER]; // 16 MB  [b*N + n][512]
__device__ double g_score[BSZ * NTOK];
__device__ float  g_nnz[NTOK];
__device__ int    g_src[BSZ * NTOK];           // per-batch source row map

// ---------------- zero score ------------------------------------------------
__global__ void zero_score_kernel() {
    int i = blockIdx.x * blockDim.x + threadIdx.x;
    if (i < BSZ * NTOK) g_score[i] = 0.0;
}

// ---------------- nnz per mask row ------------------------------------------
__global__ void nnz_kernel(const int* __restrict__ mask) {
    int row = blockIdx.x;
    int t = threadIdx.x;
    int cnt = 0;
    for (int c = t; c < NTOK; c += 256) cnt += (mask[row * NTOK + c] != 0);
    for (int o = 16; o; o >>= 1) cnt += __shfl_xor_sync(0xffffffffu, cnt, o);
    __shared__ int sred[8];
    if ((t & 31) == 0) sred[t >> 5] = cnt;
    __syncthreads();
    if (t == 0) {
        int s = 0;
        for (int i = 0; i < 8; i++) s += sred[i];
        g_nnz[row] = (float)s;
    }
}

// ---------------- GEMM 1: qkv = x @ w_qkv  (8192 x 1536 x 512) --------------
__global__ __launch_bounds__(256) void gemm_qkv_kernel(
    const float* __restrict__ A, const float* __restrict__ Bw)
{
    const int BM = 128, BN = 128, BK = 16;
    __shared__ float As[BK][BM + 8];
    __shared__ float Bs[BK][BN];
    int bm = blockIdx.y * BM;
    int bn = blockIdx.x * BN;
    int tid = threadIdx.x;
    int ty = tid >> 4, tx = tid & 15;

    float acc[8][8];
#pragma unroll
    for (int i = 0; i < 8; i++)
#pragma unroll
        for (int j = 0; j < 8; j++) acc[i][j] = 0.f;

    for (int k0 = 0; k0 < DMODEL; k0 += BK) {
#pragma unroll
        for (int l = 0; l < 2; l++) {
            int idx = tid + l * 256;
            int ar = idx >> 2, ac4 = idx & 3;
            float4 av = *reinterpret_cast<const float4*>(&A[(size_t)(bm + ar) * DMODEL + k0 + ac4 * 4]);
            As[ac4 * 4 + 0][ar] = av.x;
            As[ac4 * 4 + 1][ar] = av.y;
            As[ac4 * 4 + 2][ar] = av.z;
            As[ac4 * 4 + 3][ar] = av.w;
            int br = idx >> 5, bc4 = idx & 31;
            *reinterpret_cast<float4*>(&Bs[br][bc4 * 4]) =
                *reinterpret_cast<const float4*>(&Bw[(size_t)(k0 + br) * QKV3 + bn + bc4 * 4]);
        }
        __syncthreads();
#pragma unroll
        for (int k = 0; k < BK; k++) {
            float ar8[8], br8[8];
#pragma unroll
            for (int i = 0; i < 8; i++) ar8[i] = As[k][ty * 8 + i];
#pragma unroll
            for (int j = 0; j < 8; j++) br8[j] = Bs[k][tx * 8 + j];
#pragma unroll
            for (int i = 0; i < 8; i++)
#pragma unroll
                for (int j = 0; j < 8; j++) acc[i][j] = fmaf(ar8[i], br8[j], acc[i][j]);
        }
        __syncthreads();
    }
#pragma unroll
    for (int i = 0; i < 8; i++) {
        int row = bm + ty * 8 + i;
#pragma unroll
        for (int j = 0; j < 8; j += 4) {
            float4 v = make_float4(acc[i][j], acc[i][j + 1], acc[i][j + 2], acc[i][j + 3]);
            *reinterpret_cast<float4*>(&g_qkv[(size_t)row * QKV3 + bn + tx * 8 + j]) = v;
        }
    }
}

// ---------------- fused attention + score ------------------------------------
// grid: (qtile=16, h=8, b=8), block 256 (16x16), each thread 4x4 of a 64x64 tile
#define QS_ST 64
#define KS_ST 65
__global__ __launch_bounds__(256) void attn_kernel(const int* __restrict__ mask)
{
    extern __shared__ float sm[];
    float* Qs = sm;                           // [64][64]
    float* Ks = Qs + 64 * QS_ST;              // [64][65]
    float* Vs = Ks + 64 * KS_ST;              // [64][65]
    float* Ps = Vs + 64 * KS_ST;              // [64][65]  (mask, then P)

    int qt = blockIdx.x, h = blockIdx.y, b = blockIdx.z;
    int tid = threadIdx.x;
    int ty = tid >> 4, tx = tid & 15;
    int q0 = qt * 64;

    // load Q tile
#pragma unroll
    for (int l = 0; l < 4; l++) {
        int idx = tid + l * 256;           // 1024 float4 total
        int r = idx >> 4, d4 = idx & 15;
        const float* qb = &g_qkv[(size_t)(b * NTOK + q0 + r) * QKV3 + h * DHE + d4 * 4];
        float4 v = *reinterpret_cast<const float4*>(qb);
        Qs[r * QS_ST + d4 * 4 + 0] = v.x;
        Qs[r * QS_ST + d4 * 4 + 1] = v.y;
        Qs[r * QS_ST + d4 * 4 + 2] = v.z;
        Qs[r * QS_ST + d4 * 4 + 3] = v.w;
    }

    float m_i[4], l_i[4], o[4][4];
    double sc[4];
#pragma unroll
    for (int i = 0; i < 4; i++) {
        m_i[i] = -1e30f; l_i[i] = 0.f; sc[i] = 0.0;
#pragma unroll
        for (int j = 0; j < 4; j++) o[i][j] = 0.f;
    }

    for (int kt = 0; kt < 16; kt++) {
        int k0 = kt * 64;
        // load K and V tiles
#pragma unroll
        for (int l = 0; l < 4; l++) {
            int idx = tid + l * 256;
            int r = idx >> 4, d4 = idx & 15;
            const float* kb = &g_qkv[(size_t)(b * NTOK + k0 + r) * QKV3 + DMODEL + h * DHE + d4 * 4];
            float4 kv = *reinterpret_cast<const float4*>(kb);
            Ks[r * KS_ST + d4 * 4 + 0] = kv.x;
            Ks[r * KS_ST + d4 * 4 + 1] = kv.y;
            Ks[r * KS_ST + d4 * 4 + 2] = kv.z;
            Ks[r * KS_ST + d4 * 4 + 3] = kv.w;
            float4 vv = *reinterpret_cast<const float4*>(kb + DMODEL);
            Vs[r * KS_ST + d4 * 4 + 0] = vv.x;
            Vs[r * KS_ST + d4 * 4 + 1] = vv.y;
            Vs[r * KS_ST + d4 * 4 + 2] = vv.z;
            Vs[r * KS_ST + d4 * 4 + 3] = vv.w;
            // mask tile -> Ps (as float)
            const int4 mi = *reinterpret_cast<const int4*>(&mask[(size_t)(q0 + r) * NTOK + k0 + d4 * 4]);
            Ps[r * KS_ST + d4 * 4 + 0] = (float)mi.x;
            Ps[r * KS_ST + d4 * 4 + 1] = (float)mi.y;
            Ps[r * KS_ST + d4 * 4 + 2] = (float)mi.z;
            Ps[r * KS_ST + d4 * 4 + 3] = (float)mi.w;
        }
        __syncthreads();

        // S = Q K^T
        float s[4][4];
#pragma unroll
        for (int i = 0; i < 4; i++)
#pragma unroll
            for (int j = 0; j < 4; j++) s[i][j] = 0.f;
#pragma unroll 16
        for (int d = 0; d < 64; d++) {
            float qr[4], kr[4];
#pragma unroll
            for (int i = 0; i < 4; i++) qr[i] = Qs[(ty * 4 + i) * QS_ST + d];
#pragma unroll
            for (int j = 0; j < 4; j++) kr[j] = Ks[(tx * 4 + j) * KS_ST + d];
#pragma unroll
            for (int i = 0; i < 4; i++)
#pragma unroll
                for (int j = 0; j < 4; j++) s[i][j] = fmaf(qr[i], kr[j], s[i][j]);
        }

        // mask, score, online softmax
#pragma unroll
        for (int i = 0; i < 4; i++) {
            int r = ty * 4 + i;
            float lg[4];
            float mx = -1e30f;
#pragma unroll
            for (int j = 0; j < 4; j++) {
                float mv = Ps[r * KS_ST + tx * 4 + j];
                lg[j] = s[i][j] * ASCALE * mv;
                sc[i] += (double)fabsf(lg[j]);
                mx = fmaxf(mx, lg[j]);
            }
#pragma unroll
            for (int off = 8; off; off >>= 1)
                mx = fmaxf(mx, __shfl_xor_sync(0xffffffffu, mx, off));
            float mnew = fmaxf(m_i[i], mx);
            float corr = __expf(m_i[i] - mnew);
            float p[4], ps = 0.f;
#pragma unroll
            for (int j = 0; j < 4; j++) { p[j] = __expf(lg[j] - mnew); ps += p[j]; }
#pragma unroll
            for (int off = 8; off; off >>= 1)
                ps += __shfl_xor_sync(0xffffffffu, ps, off);
            l_i[i] = l_i[i] * corr + ps;
            m_i[i] = mnew;
#pragma unroll
            for (int j = 0; j < 4; j++) {
                o[i][j] *= corr;
                Ps[r * KS_ST + tx * 4 + j] = p[j];
            }
        }
        __syncthreads();

        // O += P @ V
#pragma unroll 16
        for (int k = 0; k < 64; k++) {
            float pr[4], vr[4];
#pragma unroll
            for (int i = 0; i < 4; i++) pr[i] = Ps[(ty * 4 + i) * KS_ST + k];
#pragma unroll
            for (int j = 0; j < 4; j++) vr[j] = Vs[k * KS_ST + tx * 4 + j];
#pragma unroll
            for (int i = 0; i < 4; i++)
#pragma unroll
                for (int j = 0; j < 4; j++) o[i][j] = fmaf(pr[i], vr[j], o[i][j]);
        }
        __syncthreads();
    }

    // epilogue: write O / l, accumulate score
#pragma unroll
    for (int i = 0; i < 4; i++) {
        int q = q0 + ty * 4 + i;
        float inv = 1.0f / l_i[i];
#pragma unroll
        for (int j = 0; j < 4; j++)
            g_attn[(size_t)(b * NTOK + q) * DINNER + h * DHE + tx * 4 + j] = o[i][j] * inv;
        double ssum = sc[i];
#pragma unroll
        for (int off = 8; off; off >>= 1)
            ssum += __shfl_xor_sync(0xffffffffu, ssum, off);
        if (tx == 0) atomicAdd(&g_score[b * NTOK + q], ssum);
    }
}

// ---------------- sort + swap map --------------------------------------------
// block bb sorts score[bb] ascending; writes src map for batch (7-bb)
__global__ __launch_bounds__(1024) void sort_swap_kernel(const int* __restrict__ patches)
{
    int bb = blockIdx.x;
    int t = threadIdx.x;
    __shared__ double sval[NTOK];
    __shared__ int sidx[NTOK];
    sval[t] = g_score[bb * NTOK + t] / (double)g_nnz[t];
    sidx[t] = t;
    __syncthreads();

    for (int k = 2; k <= NTOK; k <<= 1) {
        for (int j = k >> 1; j > 0; j >>= 1) {
            int ixj = t ^ j;
            if (ixj > t) {
                double v1 = sval[t], v2 = sval[ixj];
                int i1 = sidx[t], i2 = sidx[ixj];
                bool gt = (v1 > v2) || (v1 == v2 && i1 > i2);
                bool up = ((t & k) == 0);
                if (gt == up) {
                    sval[t] = v2; sval[ixj] = v1;
                    sidx[t] = i2; sidx[ixj] = i1;
                }
            }
            __syncthreads();
        }
    }

    int bo = (BSZ - 1) - bb;   // target batch (the [::-1])
    g_src[bo * NTOK + t] = t;
    __syncthreads();
    if (t == 0) {
        int P = patches[0];
        for (int i = 1; i <= P; i++) {
            int ti = sidx[i];
            g_src[bo * NTOK + i] = ti;
            g_src[bo * NTOK + ti] = i;
        }
    }
}

// ---------------- GEMM 2: out = gather(attn) @ w_out + b_out ----------------
__global__ __launch_bounds__(256) void gemm_out_kernel(
    const float* __restrict__ Wo, const float* __restrict__ bias,
    float* __restrict__ Out)
{
    const int BM = 128, BN = 128, BK = 16;
    __shared__ float As[BK][BM + 8];
    __shared__ float Bs[BK][BN];
    __shared__ int rowmap[BM];
    int bm = blockIdx.y * BM;
    int bn = blockIdx.x * BN;
    int tid = threadIdx.x;
    int ty = tid >> 4, tx = tid & 15;

    if (tid < BM) {
        int row = bm + tid;
        rowmap[tid] = (row & ~(NTOK - 1)) + g_src[row];
    }
    __syncthreads();

    float acc[8][8];
#pragma unroll
    for (int i = 0; i < 8; i++)
#pragma unroll
        for (int j = 0; j < 8; j++) acc[i][j] = 0.f;

    for (int k0 = 0; k0 < DINNER; k0 += BK) {
#pragma unroll
        for (int l = 0; l < 2; l++) {
            int idx = tid + l * 256;
            int ar = idx >> 2, ac4 = idx & 3;
            float4 av = *reinterpret_cast<const float4*>(&g_attn[(size_t)rowmap[ar] * DINNER + k0 + ac4 * 4]);
            As[ac4 * 4 + 0][ar] = av.x;
            As[ac4 * 4 + 1][ar] = av.y;
            As[ac4 * 4 + 2][ar] = av.z;
            As[ac4 * 4 + 3][ar] = av.w;
            int br = idx >> 5, bc4 = idx & 31;
            *reinterpret_cast<float4*>(&Bs[br][bc4 * 4]) =
                *reinterpret_cast<const float4*>(&Wo[(size_t)(k0 + br) * DMODEL + bn + bc4 * 4]);
        }
        __syncthreads();
#pragma unroll
        for (int k = 0; k < BK; k++) {
            float ar8[8], br8[8];
#pragma unroll
            for (int i = 0; i < 8; i++) ar8[i] = As[k][ty * 8 + i];
#pragma unroll
            for (int j = 0; j < 8; j++) br8[j] = Bs[k][tx * 8 + j];
#pragma unroll
            for (int i = 0; i < 8; i++)
#pragma unroll
                for (int j = 0; j < 8; j++) acc[i][j] = fmaf(ar8[i], br8[j], acc[i][j]);
        }
        __syncthreads();
    }
#pragma unroll
    for (int i = 0; i < 8; i++) {
        int row = bm + ty * 8 + i;
#pragma unroll
        for (int j = 0; j < 8; j += 4) {
            int col = bn + tx * 8 + j;
            float4 v = make_float4(acc[i][j] + bias[col],
                                   acc[i][j + 1] + bias[col + 1],
                                   acc[i][j + 2] + bias[col + 2],
                                   acc[i][j + 3] + bias[col + 3]);
            *reinterpret_cast<float4*>(&Out[(size_t)row * DMODEL + col]) = v;
        }
    }
}

// ---------------- launch -----------------------------------------------------
extern "C" void kernel_launch(void* const* d_in, const int* in_sizes, int n_in,
                              void* d_out, int out_size)
{
    const float* x       = (const float*)d_in[0];
    const int*   cp_mask = (const int*)d_in[1];
    const float* w_qkv   = (const float*)d_in[2];
    const float* w_out   = (const float*)d_in[3];
    const float* b_out   = (const float*)d_in[4];
    const int*   patches = (const int*)d_in[5];
    float* out = (float*)d_out;

    const int attn_smem = (64 * QS_ST + 3 * 64 * KS_ST) * (int)sizeof(float);
    cudaFuncSetAttribute(attn_kernel, cudaFuncAttributeMaxDynamicSharedMemorySize, attn_smem);

    zero_score_kernel<<<32, 256>>>();
    nnz_kernel<<<NTOK, 256>>>(cp_mask);
    gemm_qkv_kernel<<<dim3(QKV3 / 128, (BSZ * NTOK) / 128), 256>>>(x, w_qkv);
    attn_kernel<<<dim3(16, NH, BSZ), 256, attn_smem>>>(cp_mask);
    sort_swap_kernel<<<BSZ, 1024>>>(patches);
    gemm_out_kernel<<<dim3(DMODEL / 128, (BSZ * NTOK) / 128), 256>>>(w_out, b_out, out);
}

// round 2
// speedup vs baseline: 1.1680x; 1.1680x over previous
#include <cuda_runtime.h>
#include <math.h>

#define BSZ    8
#define NTOK   1024
#define DMODEL 512
#define QKV3   1536
#define NH     8
#define DHE    64
#define DINNER 512
#define ASCALE 0.125f

// ---------------- scratch (device globals; no runtime allocation) ----------
__device__ float  g_qkv[BSZ * NTOK * QKV3];    // [b*N + n][1536]
__device__ float  g_attn[BSZ * NTOK * DINNER]; // [b*N + n][512]
__device__ double g_score[BSZ * NTOK];
__device__ float  g_nnz[NTOK];
__device__ int    g_src[BSZ * NTOK];

// ---------------- f32x2 helpers ---------------------------------------------
static __device__ __forceinline__ unsigned long long dup2(float v) {
    unsigned long long r;
    asm("mov.b64 %0, {%1, %1};" : "=l"(r) : "f"(v));
    return r;
}
static __device__ __forceinline__ void fma2(unsigned long long& d,
                                            unsigned long long a,
                                            unsigned long long b) {
    asm("fma.rn.f32x2 %0, %1, %2, %0;" : "+l"(d) : "l"(a), "l"(b));
}
static __device__ __forceinline__ void mul2ip(unsigned long long& d,
                                              unsigned long long a) {
    asm("mul.rn.f32x2 %0, %0, %1;" : "+l"(d) : "l"(a));
}
static __device__ __forceinline__ float2 unpack2(unsigned long long v) {
    float2 f;
    asm("mov.b64 {%0, %1}, %2;" : "=f"(f.x), "=f"(f.y) : "l"(v));
    return f;
}

// ---------------- zero score -------------------------------------------------
__global__ void zero_score_kernel() {
    int i = blockIdx.x * blockDim.x + threadIdx.x;
    if (i < BSZ * NTOK) g_score[i] = 0.0;
}

// ---------------- nnz per mask row -------------------------------------------
__global__ void nnz_kernel(const int* __restrict__ mask) {
    int row = blockIdx.x;
    int t = threadIdx.x;
    int cnt = 0;
    for (int c = t; c < NTOK; c += 256) cnt += (mask[row * NTOK + c] != 0);
    for (int o = 16; o; o >>= 1) cnt += __shfl_xor_sync(0xffffffffu, cnt, o);
    __shared__ int sred[8];
    if ((t & 31) == 0) sred[t >> 5] = cnt;
    __syncthreads();
    if (t == 0) {
        int s = 0;
        for (int i = 0; i < 8; i++) s += sred[i];
        g_nnz[row] = (float)s;
    }
}

// ---------------- GEMM 1: qkv = x @ w_qkv  (8192 x 1536 x 512) ---------------
__global__ __launch_bounds__(256) void gemm_qkv_kernel(
    const float* __restrict__ A, const float* __restrict__ Bw)
{
    const int BM = 128, BN = 128, BK = 16;
    __shared__ float As[BK][BM + 8];
    __shared__ float Bs[BK][BN];
    int bm = blockIdx.y * BM;
    int bn = blockIdx.x * BN;
    int tid = threadIdx.x;
    int ty = tid >> 4, tx = tid & 15;

    unsigned long long acc[8][4];
#pragma unroll
    for (int i = 0; i < 8; i++)
#pragma unroll
        for (int j = 0; j < 4; j++) acc[i][j] = 0ULL;

    for (int k0 = 0; k0 < DMODEL; k0 += BK) {
#pragma unroll
        for (int l = 0; l < 2; l++) {
            int idx = tid + l * 256;
            int ar = idx >> 2, ac4 = idx & 3;
            float4 av = *reinterpret_cast<const float4*>(&A[(size_t)(bm + ar) * DMODEL + k0 + ac4 * 4]);
            As[ac4 * 4 + 0][ar] = av.x;
            As[ac4 * 4 + 1][ar] = av.y;
            As[ac4 * 4 + 2][ar] = av.z;
            As[ac4 * 4 + 3][ar] = av.w;
            int br = idx >> 5, bc4 = idx & 31;
            *reinterpret_cast<float4*>(&Bs[br][bc4 * 4]) =
                *reinterpret_cast<const float4*>(&Bw[(size_t)(k0 + br) * QKV3 + bn + bc4 * 4]);
        }
        __syncthreads();
#pragma unroll
        for (int k = 0; k < BK; k++) {
            float4 a0 = *reinterpret_cast<const float4*>(&As[k][ty * 8]);
            float4 a1 = *reinterpret_cast<const float4*>(&As[k][ty * 8 + 4]);
            ulonglong2 b01 = *reinterpret_cast<const ulonglong2*>(&Bs[k][tx * 8]);
            ulonglong2 b23 = *reinterpret_cast<const ulonglong2*>(&Bs[k][tx * 8 + 4]);
            float av[8] = {a0.x, a0.y, a0.z, a0.w, a1.x, a1.y, a1.z, a1.w};
#pragma unroll
            for (int i = 0; i < 8; i++) {
                unsigned long long ad = dup2(av[i]);
                fma2(acc[i][0], ad, b01.x);
                fma2(acc[i][1], ad, b01.y);
                fma2(acc[i][2], ad, b23.x);
                fma2(acc[i][3], ad, b23.y);
            }
        }
        __syncthreads();
    }
#pragma unroll
    for (int i = 0; i < 8; i++) {
        int row = bm + ty * 8 + i;
        float2 c0 = unpack2(acc[i][0]), c1 = unpack2(acc[i][1]);
        float2 c2 = unpack2(acc[i][2]), c3 = unpack2(acc[i][3]);
        *reinterpret_cast<float4*>(&g_qkv[(size_t)row * QKV3 + bn + tx * 8]) =
            make_float4(c0.x, c0.y, c1.x, c1.y);
        *reinterpret_cast<float4*>(&g_qkv[(size_t)row * QKV3 + bn + tx * 8 + 4]) =
            make_float4(c2.x, c2.y, c3.x, c3.y);
    }
}

// ---------------- fused attention + score ------------------------------------
// grid (8 qtiles, 8 h, 8 b), block 256 (16x16). Tile 128q x 128k, 8x8/thread.
#define QTS 132   // Qt [d][q]
#define KTS 132   // Kt [d][k]
#define VTS 68    // Vs [k][d]
#define PTS 132   // Ps [q][k]
__global__ __launch_bounds__(256, 1) void attn_kernel(const int* __restrict__ mask)
{
    extern __shared__ float sm[];
    float* Qt = sm;                       // [64][132]
    float* Kt = Qt + 64 * QTS;            // [64][132]
    float* Vs = Kt + 64 * KTS;            // [128][68]
    float* Ps = Vs + 128 * VTS;           // [128][132]

    int qt = blockIdx.x, h = blockIdx.y, b = blockIdx.z;
    int tid = threadIdx.x;
    int ty = tid >> 4, tx = tid & 15;
    int q0 = qt * 128;

    // ---- load Q transposed [d][q] (4-row register transpose) ----
    {
        const float* qbase = g_qkv + (size_t)(b * NTOK + q0) * QKV3 + h * DHE;
#pragma unroll
        for (int l = 0; l < 2; l++) {
            int idx = tid + l * 256;        // 512 work items
            int r4 = idx >> 4, d4 = idx & 15;
            const float* p = qbase + (size_t)(4 * r4) * QKV3 + d4 * 4;
            float4 a0 = *reinterpret_cast<const float4*>(p);
            float4 a1 = *reinterpret_cast<const float4*>(p + QKV3);
            float4 a2 = *reinterpret_cast<const float4*>(p + 2 * QKV3);
            float4 a3 = *reinterpret_cast<const float4*>(p + 3 * QKV3);
            *reinterpret_cast<float4*>(&Qt[(d4 * 4 + 0) * QTS + 4 * r4]) = make_float4(a0.x, a1.x, a2.x, a3.x);
            *reinterpret_cast<float4*>(&Qt[(d4 * 4 + 1) * QTS + 4 * r4]) = make_float4(a0.y, a1.y, a2.y, a3.y);
            *reinterpret_cast<float4*>(&Qt[(d4 * 4 + 2) * QTS + 4 * r4]) = make_float4(a0.z, a1.z, a2.z, a3.z);
            *reinterpret_cast<float4*>(&Qt[(d4 * 4 + 3) * QTS + 4 * r4]) = make_float4(a0.w, a1.w, a2.w, a3.w);
        }
    }

    unsigned long long o2[8][2];
    float m_i[8], l_i[8];
    double scd[8];
#pragma unroll
    for (int i = 0; i < 8; i++) {
        o2[i][0] = 0ULL; o2[i][1] = 0ULL;
        m_i[i] = -1e30f; l_i[i] = 0.f; scd[i] = 0.0;
    }

    for (int kt = 0; kt < 8; kt++) {
        int k0 = kt * 128;
        // ---- K transposed [d][k] ----
        const float* kbase = g_qkv + (size_t)(b * NTOK + k0) * QKV3 + DMODEL + h * DHE;
#pragma unroll
        for (int l = 0; l < 2; l++) {
            int idx = tid + l * 256;
            int r4 = idx >> 4, d4 = idx & 15;
            const float* p = kbase + (size_t)(4 * r4) * QKV3 + d4 * 4;
            float4 a0 = *reinterpret_cast<const float4*>(p);
            float4 a1 = *reinterpret_cast<const float4*>(p + QKV3);
            float4 a2 = *reinterpret_cast<const float4*>(p + 2 * QKV3);
            float4 a3 = *reinterpret_cast<const float4*>(p + 3 * QKV3);
            *reinterpret_cast<float4*>(&Kt[(d4 * 4 + 0) * KTS + 4 * r4]) = make_float4(a0.x, a1.x, a2.x, a3.x);
            *reinterpret_cast<float4*>(&Kt[(d4 * 4 + 1) * KTS + 4 * r4]) = make_float4(a0.y, a1.y, a2.y, a3.y);
            *reinterpret_cast<float4*>(&Kt[(d4 * 4 + 2) * KTS + 4 * r4]) = make_float4(a0.z, a1.z, a2.z, a3.z);
            *reinterpret_cast<float4*>(&Kt[(d4 * 4 + 3) * KTS + 4 * r4]) = make_float4(a0.w, a1.w, a2.w, a3.w);
        }
        // ---- V natural [k][d] ----
        const float* vbase = g_qkv + (size_t)(b * NTOK + k0) * QKV3 + 2 * DMODEL + h * DHE;
#pragma unroll
        for (int l = 0; l < 8; l++) {
            int idx = tid + l * 256;        // 2048 float4
            int r = idx >> 4, d4 = idx & 15;
            *reinterpret_cast<float4*>(&Vs[r * VTS + d4 * 4]) =
                *reinterpret_cast<const float4*>(vbase + (size_t)r * QKV3 + d4 * 4);
        }
        __syncthreads();

        // ---- S = Q K^T (f32x2) ----
        unsigned long long s2[8][4];
#pragma unroll
        for (int i = 0; i < 8; i++)
#pragma unroll
            for (int j = 0; j < 4; j++) s2[i][j] = 0ULL;

#pragma unroll 4
        for (int d = 0; d < 64; d++) {
            float4 qa = *reinterpret_cast<const float4*>(&Qt[d * QTS + ty * 8]);
            float4 qb = *reinterpret_cast<const float4*>(&Qt[d * QTS + ty * 8 + 4]);
            ulonglong2 k01 = *reinterpret_cast<const ulonglong2*>(&Kt[d * KTS + tx * 8]);
            ulonglong2 k23 = *reinterpret_cast<const ulonglong2*>(&Kt[d * KTS + tx * 8 + 4]);
            float qv[8] = {qa.x, qa.y, qa.z, qa.w, qb.x, qb.y, qb.z, qb.w};
#pragma unroll
            for (int i = 0; i < 8; i++) {
                unsigned long long qd = dup2(qv[i]);
                fma2(s2[i][0], qd, k01.x);
                fma2(s2[i][1], qd, k01.y);
                fma2(s2[i][2], qd, k23.x);
                fma2(s2[i][3], qd, k23.y);
            }
        }

        // ---- mask, score, online softmax, P store ----
        const int* mbase = mask + (size_t)(q0 + ty * 8) * NTOK + k0 + tx * 8;
#pragma unroll
        for (int i = 0; i < 8; i++) {
            int4 ma = *reinterpret_cast<const int4*>(mbase + (size_t)i * NTOK);
            int4 mb = *reinterpret_cast<const int4*>(mbase + (size_t)i * NTOK + 4);
            float2 v0 = unpack2(s2[i][0]), v1 = unpack2(s2[i][1]);
            float2 v2 = unpack2(s2[i][2]), v3 = unpack2(s2[i][3]);
            float lg[8];
            lg[0] = v0.x * (ASCALE * (float)ma.x);
            lg[1] = v0.y * (ASCALE * (float)ma.y);
            lg[2] = v1.x * (ASCALE * (float)ma.z);
            lg[3] = v1.y * (ASCALE * (float)ma.w);
            lg[4] = v2.x * (ASCALE * (float)mb.x);
            lg[5] = v2.y * (ASCALE * (float)mb.y);
            lg[6] = v3.x * (ASCALE * (float)mb.z);
            lg[7] = v3.y * (ASCALE * (float)mb.w);
            float ssum = 0.f, mx = -1e30f;
#pragma unroll
            for (int j = 0; j < 8; j++) {
                ssum += fabsf(lg[j]);
                mx = fmaxf(mx, lg[j]);
            }
            scd[i] += (double)ssum;
#pragma unroll
            for (int off = 8; off; off >>= 1)
                mx = fmaxf(mx, __shfl_xor_sync(0xffffffffu, mx, off));
            float mnew = fmaxf(m_i[i], mx);
            float corr = __expf(m_i[i] - mnew);
            float p[8], ps = 0.f;
#pragma unroll
            for (int j = 0; j < 8; j++) { p[j] = __expf(lg[j] - mnew); ps += p[j]; }
#pragma unroll
            for (int off = 8; off; off >>= 1)
                ps += __shfl_xor_sync(0xffffffffu, ps, off);
            l_i[i] = l_i[i] * corr + ps;
            m_i[i] = mnew;
            unsigned long long cd = dup2(corr);
            mul2ip(o2[i][0], cd);
            mul2ip(o2[i][1], cd);
            *reinterpret_cast<float4*>(&Ps[(ty * 8 + i) * PTS + tx * 8]) =
                make_float4(p[0], p[1], p[2], p[3]);
            *reinterpret_cast<float4*>(&Ps[(ty * 8 + i) * PTS + tx * 8 + 4]) =
                make_float4(p[4], p[5], p[6], p[7]);
        }
        __syncthreads();

        // ---- O += P @ V (f32x2), o2[i] covers d-cols tx*4..tx*4+3 ----
        for (int k = 0; k < 128; k += 4) {
            ulonglong2 va = *reinterpret_cast<const ulonglong2*>(&Vs[(k + 0) * VTS + tx * 4]);
            ulonglong2 vb = *reinterpret_cast<const ulonglong2*>(&Vs[(k + 1) * VTS + tx * 4]);
            ulonglong2 vc = *reinterpret_cast<const ulonglong2*>(&Vs[(k + 2) * VTS + tx * 4]);
            ulonglong2 vd = *reinterpret_cast<const ulonglong2*>(&Vs[(k + 3) * VTS + tx * 4]);
#pragma unroll
            for (int i = 0; i < 8; i++) {
                float4 pv = *reinterpret_cast<const float4*>(&Ps[(ty * 8 + i) * PTS + k]);
                unsigned long long pd;
                pd = dup2(pv.x); fma2(o2[i][0], pd, va.x); fma2(o2[i][1], pd, va.y);
                pd = dup2(pv.y); fma2(o2[i][0], pd, vb.x); fma2(o2[i][1], pd, vb.y);
                pd = dup2(pv.z); fma2(o2[i][0], pd, vc.x); fma2(o2[i][1], pd, vc.y);
                pd = dup2(pv.w); fma2(o2[i][0], pd, vd.x); fma2(o2[i][1], pd, vd.y);
            }
        }
        __syncthreads();
    }

    // ---- epilogue ----
#pragma unroll
    for (int i = 0; i < 8; i++) {
        int q = q0 + ty * 8 + i;
        float inv = 1.0f / l_i[i];
        float2 oa = unpack2(o2[i][0]);
        float2 ob = unpack2(o2[i][1]);
        *reinterpret_cast<float4*>(&g_attn[(size_t)(b * NTOK + q) * DINNER + h * DHE + tx * 4]) =
            make_float4(oa.x * inv, oa.y * inv, ob.x * inv, ob.y * inv);
        double ssum = scd[i];
#pragma unroll
        for (int off = 8; off; off >>= 1)
            ssum += __shfl_xor_sync(0xffffffffu, ssum, off);
        if (tx == 0) atomicAdd(&g_score[b * NTOK + q], ssum);
    }
}

// ---------------- sort + swap map --------------------------------------------
__global__ __launch_bounds__(1024) void sort_swap_kernel(const int* __restrict__ patches)
{
    int bb = blockIdx.x;
    int t = threadIdx.x;
    __shared__ double sval[NTOK];
    __shared__ int sidx[NTOK];
    sval[t] = g_score[bb * NTOK + t] / (double)g_nnz[t];
    sidx[t] = t;
    __syncthreads();

    for (int k = 2; k <= NTOK; k <<= 1) {
        for (int j = k >> 1; j > 0; j >>= 1) {
            int ixj = t ^ j;
            if (ixj > t) {
                double v1 = sval[t], v2 = sval[ixj];
                int i1 = sidx[t], i2 = sidx[ixj];
                bool gt = (v1 > v2) || (v1 == v2 && i1 > i2);
                bool up = ((t & k) == 0);
                if (gt == up) {
                    sval[t] = v2; sval[ixj] = v1;
                    sidx[t] = i2; sidx[ixj] = i1;
                }
            }
            __syncthreads();
        }
    }

    int bo = (BSZ - 1) - bb;
    g_src[bo * NTOK + t] = t;
    __syncthreads();
    if (t == 0) {
        int P = patches[0];
        for (int i = 1; i <= P; i++) {
            int ti = sidx[i];
            g_src[bo * NTOK + i] = ti;
            g_src[bo * NTOK + ti] = i;
        }
    }
}

// ---------------- GEMM 2: out = gather(attn) @ w_out + b_out -----------------
__global__ __launch_bounds__(256) void gemm_out_kernel(
    const float* __restrict__ Wo, const float* __restrict__ bias,
    float* __restrict__ Out)
{
    const int BM = 128, BN = 128, BK = 16;
    __shared__ float As[BK][BM + 8];
    __shared__ float Bs[BK][BN];
    __shared__ int rowmap[BM];
    int bm = blockIdx.y * BM;
    int bn = blockIdx.x * BN;
    int tid = threadIdx.x;
    int ty = tid >> 4, tx = tid & 15;

    if (tid < BM) {
        int row = bm + tid;
        rowmap[tid] = (row & ~(NTOK - 1)) + g_src[row];
    }
    __syncthreads();

    unsigned long long acc[8][4];
#pragma unroll
    for (int i = 0; i < 8; i++)
#pragma unroll
        for (int j = 0; j < 4; j++) acc[i][j] = 0ULL;

    for (int k0 = 0; k0 < DINNER; k0 += BK) {
#pragma unroll
        for (int l = 0; l < 2; l++) {
            int idx = tid + l * 256;
            int ar = idx >> 2, ac4 = idx & 3;
            float4 av = *reinterpret_cast<const float4*>(&g_attn[(size_t)rowmap[ar] * DINNER + k0 + ac4 * 4]);
            As[ac4 * 4 + 0][ar] = av.x;
            As[ac4 * 4 + 1][ar] = av.y;
            As[ac4 * 4 + 2][ar] = av.z;
            As[ac4 * 4 + 3][ar] = av.w;
            int br = idx >> 5, bc4 = idx & 31;
            *reinterpret_cast<float4*>(&Bs[br][bc4 * 4]) =
                *reinterpret_cast<const float4*>(&Wo[(size_t)(k0 + br) * DMODEL + bn + bc4 * 4]);
        }
        __syncthreads();
#pragma unroll
        for (int k = 0; k < BK; k++) {
            float4 a0 = *reinterpret_cast<const float4*>(&As[k][ty * 8]);
            float4 a1 = *reinterpret_cast<const float4*>(&As[k][ty * 8 + 4]);
            ulonglong2 b01 = *reinterpret_cast<const ulonglong2*>(&Bs[k][tx * 8]);
            ulonglong2 b23 = *reinterpret_cast<const ulonglong2*>(&Bs[k][tx * 8 + 4]);
            float av[8] = {a0.x, a0.y, a0.z, a0.w, a1.x, a1.y, a1.z, a1.w};
#pragma unroll
            for (int i = 0; i < 8; i++) {
                unsigned long long ad = dup2(av[i]);
                fma2(acc[i][0], ad, b01.x);
                fma2(acc[i][1], ad, b01.y);
                fma2(acc[i][2], ad, b23.x);
                fma2(acc[i][3], ad, b23.y);
            }
        }
        __syncthreads();
    }
#pragma unroll
    for (int i = 0; i < 8; i++) {
        int row = bm + ty * 8 + i;
        int col = bn + tx * 8;
        float2 c0 = unpack2(acc[i][0]), c1 = unpack2(acc[i][1]);
        float2 c2 = unpack2(acc[i][2]), c3 = unpack2(acc[i][3]);
        *reinterpret_cast<float4*>(&Out[(size_t)row * DMODEL + col]) =
            make_float4(c0.x + bias[col + 0], c0.y + bias[col + 1],
                        c1.x + bias[col + 2], c1.y + bias[col + 3]);
        *reinterpret_cast<float4*>(&Out[(size_t)row * DMODEL + col + 4]) =
            make_float4(c2.x + bias[col + 4], c2.y + bias[col + 5],
                        c3.x + bias[col + 6], c3.y + bias[col + 7]);
    }
}

// ---------------- launch ------------------------------------------------------
extern "C" void kernel_launch(void* const* d_in, const int* in_sizes, int n_in,
                              void* d_out, int out_size)
{
    const float* x       = (const float*)d_in[0];
    const int*   cp_mask = (const int*)d_in[1];
    const float* w_qkv   = (const float*)d_in[2];
    const float* w_out   = (const float*)d_in[3];
    const float* b_out   = (const float*)d_in[4];
    const int*   patches = (const int*)d_in[5];
    float* out = (float*)d_out;

    const int attn_smem = (64 * QTS + 64 * KTS + 128 * VTS + 128 * PTS) * (int)sizeof(float);
    cudaFuncSetAttribute(attn_kernel, cudaFuncAttributeMaxDynamicSharedMemorySize, attn_smem);

    zero_score_kernel<<<32, 256>>>();
    nnz_kernel<<<NTOK, 256>>>(cp_mask);
    gemm_qkv_kernel<<<dim3(QKV3 / 128, (BSZ * NTOK) / 128), 256>>>(x, w_qkv);
    attn_kernel<<<dim3(8, NH, BSZ), 256, attn_smem>>>(cp_mask);
    sort_swap_kernel<<<BSZ, 1024>>>(patches);
    gemm_out_kernel<<<dim3(DMODEL / 128, (BSZ * NTOK) / 128), 256>>>(w_out, b_out, out);
}

// round 3
// speedup vs baseline: 1.1725x; 1.0039x over previous
#include <cuda_runtime.h>
#include <math.h>

#define BSZ    8
#define NTOK   1024
#define DMODEL 512
#define QKV3   1536
#define NH     8
#define DHE    64
#define DINNER 512
#define ASCALE 0.125f

// ---------------- scratch (device globals; no runtime allocation) ----------
__device__ float  g_qkv[BSZ * NTOK * QKV3];    // [b*N + n][1536]
__device__ float  g_attn[BSZ * NTOK * DINNER]; // [b*N + n][512]
__device__ double g_score[BSZ * NTOK];
__device__ float  g_nnz[NTOK];
__device__ int    g_src[BSZ * NTOK];

// ---------------- f32x2 helpers ---------------------------------------------
static __device__ __forceinline__ unsigned long long dup2(float v) {
    unsigned long long r;
    asm("mov.b64 %0, {%1, %1};" : "=l"(r) : "f"(v));
    return r;
}
static __device__ __forceinline__ void fma2(unsigned long long& d,
                                            unsigned long long a,
                                            unsigned long long b) {
    asm("fma.rn.f32x2 %0, %1, %2, %0;" : "+l"(d) : "l"(a), "l"(b));
}
static __device__ __forceinline__ float2 unpack2(unsigned long long v) {
    float2 f;
    asm("mov.b64 {%0, %1}, %2;" : "=f"(f.x), "=f"(f.y) : "l"(v));
    return f;
}

// ---------------- zero score -------------------------------------------------
__global__ void zero_score_kernel() {
    int i = blockIdx.x * blockDim.x + threadIdx.x;
    if (i < BSZ * NTOK) g_score[i] = 0.0;
}

// ---------------- nnz per mask row -------------------------------------------
__global__ void nnz_kernel(const int* __restrict__ mask) {
    int row = blockIdx.x;
    int t = threadIdx.x;
    int cnt = 0;
    for (int c = t; c < NTOK; c += 256) cnt += (mask[row * NTOK + c] != 0);
    for (int o = 16; o; o >>= 1) cnt += __shfl_xor_sync(0xffffffffu, cnt, o);
    __shared__ int sred[8];
    if ((t & 31) == 0) sred[t >> 5] = cnt;
    __syncthreads();
    if (t == 0) {
        int s = 0;
        for (int i = 0; i < 8; i++) s += sred[i];
        g_nnz[row] = (float)s;
    }
}

// ---------------- GEMM 1: qkv = x @ w_qkv  (8192 x 1536 x 512) ---------------
// double-buffered smem, f32x2 math
__global__ __launch_bounds__(256) void gemm_qkv_kernel(
    const float* __restrict__ A, const float* __restrict__ Bw)
{
    const int BM = 128, BN = 128, BK = 16;
    __shared__ float As[2][BK][BM + 8];
    __shared__ float Bs[2][BK][BN];
    int bm = blockIdx.y * BM;
    int bn = blockIdx.x * BN;
    int tid = threadIdx.x;
    int ty = tid >> 4, tx = tid & 15;

    float4 pa[2], pb[2];
    int ar[2], ac4[2], br[2], bc4[2];
#pragma unroll
    for (int l = 0; l < 2; l++) {
        int idx = tid + l * 256;
        ar[l] = idx >> 2;  ac4[l] = idx & 3;
        br[l] = idx >> 5;  bc4[l] = idx & 31;
    }

    unsigned long long acc[8][4];
#pragma unroll
    for (int i = 0; i < 8; i++)
#pragma unroll
        for (int j = 0; j < 4; j++) acc[i][j] = 0ULL;

    // prologue: tile 0
#pragma unroll
    for (int l = 0; l < 2; l++) {
        pa[l] = *reinterpret_cast<const float4*>(&A[(size_t)(bm + ar[l]) * DMODEL + ac4[l] * 4]);
        pb[l] = *reinterpret_cast<const float4*>(&Bw[(size_t)br[l] * QKV3 + bn + bc4[l] * 4]);
    }
#pragma unroll
    for (int l = 0; l < 2; l++) {
        As[0][ac4[l] * 4 + 0][ar[l]] = pa[l].x;
        As[0][ac4[l] * 4 + 1][ar[l]] = pa[l].y;
        As[0][ac4[l] * 4 + 2][ar[l]] = pa[l].z;
        As[0][ac4[l] * 4 + 3][ar[l]] = pa[l].w;
        *reinterpret_cast<float4*>(&Bs[0][br[l]][bc4[l] * 4]) = pb[l];
    }
    __syncthreads();

    int buf = 0;
    for (int k0 = 0; k0 < DMODEL; k0 += BK) {
        if (k0 + BK < DMODEL) {
#pragma unroll
            for (int l = 0; l < 2; l++) {
                pa[l] = *reinterpret_cast<const float4*>(&A[(size_t)(bm + ar[l]) * DMODEL + k0 + BK + ac4[l] * 4]);
                pb[l] = *reinterpret_cast<const float4*>(&Bw[(size_t)(k0 + BK + br[l]) * QKV3 + bn + bc4[l] * 4]);
            }
        }
#pragma unroll
        for (int k = 0; k < BK; k++) {
            float4 a0 = *reinterpret_cast<const float4*>(&As[buf][k][ty * 8]);
            float4 a1 = *reinterpret_cast<const float4*>(&As[buf][k][ty * 8 + 4]);
            ulonglong2 b01 = *reinterpret_cast<const ulonglong2*>(&Bs[buf][k][tx * 8]);
            ulonglong2 b23 = *reinterpret_cast<const ulonglong2*>(&Bs[buf][k][tx * 8 + 4]);
            float av[8] = {a0.x, a0.y, a0.z, a0.w, a1.x, a1.y, a1.z, a1.w};
#pragma unroll
            for (int i = 0; i < 8; i++) {
                unsigned long long ad = dup2(av[i]);
                fma2(acc[i][0], ad, b01.x);
                fma2(acc[i][1], ad, b01.y);
                fma2(acc[i][2], ad, b23.x);
                fma2(acc[i][3], ad, b23.y);
            }
        }
        if (k0 + BK < DMODEL) {
            int nb = buf ^ 1;
#pragma unroll
            for (int l = 0; l < 2; l++) {
                As[nb][ac4[l] * 4 + 0][ar[l]] = pa[l].x;
                As[nb][ac4[l] * 4 + 1][ar[l]] = pa[l].y;
                As[nb][ac4[l] * 4 + 2][ar[l]] = pa[l].z;
                As[nb][ac4[l] * 4 + 3][ar[l]] = pa[l].w;
                *reinterpret_cast<float4*>(&Bs[nb][br[l]][bc4[l] * 4]) = pb[l];
            }
            __syncthreads();
            buf = nb;
        }
    }
#pragma unroll
    for (int i = 0; i < 8; i++) {
        int row = bm + ty * 8 + i;
        float2 c0 = unpack2(acc[i][0]), c1 = unpack2(acc[i][1]);
        float2 c2 = unpack2(acc[i][2]), c3 = unpack2(acc[i][3]);
        *reinterpret_cast<float4*>(&g_qkv[(size_t)row * QKV3 + bn + tx * 8]) =
            make_float4(c0.x, c0.y, c1.x, c1.y);
        *reinterpret_cast<float4*>(&g_qkv[(size_t)row * QKV3 + bn + tx * 8 + 4]) =
            make_float4(c2.x, c2.y, c3.x, c3.y);
    }
}

// ---------------- fused attention + score ------------------------------------
// grid (8 qtiles, 8 h, 8 b), block 256 (16x16). Tile 128q x 128k, 8x8/thread.
// No max-subtraction in softmax (logits bounded): l is a plain running sum.
#define QTS 132
#define KTS 132
#define VTS 68
#define PTS 132
__global__ __launch_bounds__(256, 1) void attn_kernel(const int* __restrict__ mask)
{
    extern __shared__ float sm[];
    float* Qt = sm;                       // [64][132]  (d-major)
    float* Kt = Qt + 64 * QTS;            // [64][132]
    float* Vs = Kt + 64 * KTS;            // [128][68]
    float* Ps = Vs + 128 * VTS;           // [128][132]

    int qt = blockIdx.x, h = blockIdx.y, b = blockIdx.z;
    int tid = threadIdx.x;
    int ty = tid >> 4, tx = tid & 15;
    int q0 = qt * 128;

    // ---- load Q transposed [d][q] ----
    {
        const float* qbase = g_qkv + (size_t)(b * NTOK + q0) * QKV3 + h * DHE;
#pragma unroll
        for (int l = 0; l < 2; l++) {
            int idx = tid + l * 256;
            int r4 = idx >> 4, d4 = idx & 15;
            const float* p = qbase + (size_t)(4 * r4) * QKV3 + d4 * 4;
            float4 a0 = *reinterpret_cast<const float4*>(p);
            float4 a1 = *reinterpret_cast<const float4*>(p + QKV3);
            float4 a2 = *reinterpret_cast<const float4*>(p + 2 * QKV3);
            float4 a3 = *reinterpret_cast<const float4*>(p + 3 * QKV3);
            *reinterpret_cast<float4*>(&Qt[(d4 * 4 + 0) * QTS + 4 * r4]) = make_float4(a0.x, a1.x, a2.x, a3.x);
            *reinterpret_cast<float4*>(&Qt[(d4 * 4 + 1) * QTS + 4 * r4]) = make_float4(a0.y, a1.y, a2.y, a3.y);
            *reinterpret_cast<float4*>(&Qt[(d4 * 4 + 2) * QTS + 4 * r4]) = make_float4(a0.z, a1.z, a2.z, a3.z);
            *reinterpret_cast<float4*>(&Qt[(d4 * 4 + 3) * QTS + 4 * r4]) = make_float4(a0.w, a1.w, a2.w, a3.w);
        }
    }

    unsigned long long o2[8][2];
    float l_i[8];
    double scd[8];
#pragma unroll
    for (int i = 0; i < 8; i++) {
        o2[i][0] = 0ULL; o2[i][1] = 0ULL;
        l_i[i] = 0.f; scd[i] = 0.0;
    }

    for (int kt = 0; kt < 8; kt++) {
        int k0 = kt * 128;
        // ---- K transposed [d][k] ----
        const float* kbase = g_qkv + (size_t)(b * NTOK + k0) * QKV3 + DMODEL + h * DHE;
#pragma unroll
        for (int l = 0; l < 2; l++) {
            int idx = tid + l * 256;
            int r4 = idx >> 4, d4 = idx & 15;
            const float* p = kbase + (size_t)(4 * r4) * QKV3 + d4 * 4;
            float4 a0 = *reinterpret_cast<const float4*>(p);
            float4 a1 = *reinterpret_cast<const float4*>(p + QKV3);
            float4 a2 = *reinterpret_cast<const float4*>(p + 2 * QKV3);
            float4 a3 = *reinterpret_cast<const float4*>(p + 3 * QKV3);
            *reinterpret_cast<float4*>(&Kt[(d4 * 4 + 0) * KTS + 4 * r4]) = make_float4(a0.x, a1.x, a2.x, a3.x);
            *reinterpret_cast<float4*>(&Kt[(d4 * 4 + 1) * KTS + 4 * r4]) = make_float4(a0.y, a1.y, a2.y, a3.y);
            *reinterpret_cast<float4*>(&Kt[(d4 * 4 + 2) * KTS + 4 * r4]) = make_float4(a0.z, a1.z, a2.z, a3.z);
            *reinterpret_cast<float4*>(&Kt[(d4 * 4 + 3) * KTS + 4 * r4]) = make_float4(a0.w, a1.w, a2.w, a3.w);
        }
        // ---- V natural [k][d] ----
        const float* vbase = g_qkv + (size_t)(b * NTOK + k0) * QKV3 + 2 * DMODEL + h * DHE;
#pragma unroll
        for (int l = 0; l < 8; l++) {
            int idx = tid + l * 256;
            int r = idx >> 4, d4 = idx & 15;
            *reinterpret_cast<float4*>(&Vs[r * VTS + d4 * 4]) =
                *reinterpret_cast<const float4*>(vbase + (size_t)r * QKV3 + d4 * 4);
        }
        __syncthreads();

        // ---- S = Q K^T (f32x2) ----
        unsigned long long s2[8][4];
#pragma unroll
        for (int i = 0; i < 8; i++)
#pragma unroll
            for (int j = 0; j < 4; j++) s2[i][j] = 0ULL;

#pragma unroll 4
        for (int d = 0; d < 64; d++) {
            float4 qa = *reinterpret_cast<const float4*>(&Qt[d * QTS + ty * 8]);
            float4 qb = *reinterpret_cast<const float4*>(&Qt[d * QTS + ty * 8 + 4]);
            ulonglong2 k01 = *reinterpret_cast<const ulonglong2*>(&Kt[d * KTS + tx * 8]);
            ulonglong2 k23 = *reinterpret_cast<const ulonglong2*>(&Kt[d * KTS + tx * 8 + 4]);
            float qv[8] = {qa.x, qa.y, qa.z, qa.w, qb.x, qb.y, qb.z, qb.w};
#pragma unroll
            for (int i = 0; i < 8; i++) {
                unsigned long long qd = dup2(qv[i]);
                fma2(s2[i][0], qd, k01.x);
                fma2(s2[i][1], qd, k01.y);
                fma2(s2[i][2], qd, k23.x);
                fma2(s2[i][3], qd, k23.y);
            }
        }

        // ---- mask, score, exp (no max), P store. Mask LDG pipelined. ----
        const int* mbase = mask + (size_t)(q0 + ty * 8) * NTOK + k0 + tx * 8;
        int4 ma = *reinterpret_cast<const int4*>(mbase);
        int4 mb = *reinterpret_cast<const int4*>(mbase + 4);
#pragma unroll
        for (int i = 0; i < 8; i++) {
            int4 na, nb;
            if (i < 7) {
                na = *reinterpret_cast<const int4*>(mbase + (size_t)(i + 1) * NTOK);
                nb = *reinterpret_cast<const int4*>(mbase + (size_t)(i + 1) * NTOK + 4);
            }
            float2 v0 = unpack2(s2[i][0]), v1 = unpack2(s2[i][1]);
            float2 v2 = unpack2(s2[i][2]), v3 = unpack2(s2[i][3]);
            float lg[8];
            lg[0] = v0.x * (ASCALE * (float)ma.x);
            lg[1] = v0.y * (ASCALE * (float)ma.y);
            lg[2] = v1.x * (ASCALE * (float)ma.z);
            lg[3] = v1.y * (ASCALE * (float)ma.w);
            lg[4] = v2.x * (ASCALE * (float)mb.x);
            lg[5] = v2.y * (ASCALE * (float)mb.y);
            lg[6] = v3.x * (ASCALE * (float)mb.z);
            lg[7] = v3.y * (ASCALE * (float)mb.w);
            float ssum = 0.f, lsum = 0.f;
            float p[8];
#pragma unroll
            for (int j = 0; j < 8; j++) ssum += fabsf(lg[j]);
#pragma unroll
            for (int j = 0; j < 8; j++) p[j] = __expf(lg[j]);
#pragma unroll
            for (int j = 0; j < 8; j++) lsum += p[j];
            scd[i] += (double)ssum;
            l_i[i] += lsum;
            *reinterpret_cast<float4*>(&Ps[(ty * 8 + i) * PTS + tx * 8]) =
                make_float4(p[0], p[1], p[2], p[3]);
            *reinterpret_cast<float4*>(&Ps[(ty * 8 + i) * PTS + tx * 8 + 4]) =
                make_float4(p[4], p[5], p[6], p[7]);
            ma = na; mb = nb;
        }
        __syncthreads();

        // ---- O += P @ V (f32x2), o2[i] covers d-cols tx*4..tx*4+3 ----
        for (int k = 0; k < 128; k += 4) {
            ulonglong2 va = *reinterpret_cast<const ulonglong2*>(&Vs[(k + 0) * VTS + tx * 4]);
            ulonglong2 vb = *reinterpret_cast<const ulonglong2*>(&Vs[(k + 1) * VTS + tx * 4]);
            ulonglong2 vc = *reinterpret_cast<const ulonglong2*>(&Vs[(k + 2) * VTS + tx * 4]);
            ulonglong2 vd = *reinterpret_cast<const ulonglong2*>(&Vs[(k + 3) * VTS + tx * 4]);
#pragma unroll
            for (int i = 0; i < 8; i++) {
                float4 pv = *reinterpret_cast<const float4*>(&Ps[(ty * 8 + i) * PTS + k]);
                unsigned long long pd;
                pd = dup2(pv.x); fma2(o2[i][0], pd, va.x); fma2(o2[i][1], pd, va.y);
                pd = dup2(pv.y); fma2(o2[i][0], pd, vb.x); fma2(o2[i][1], pd, vb.y);
                pd = dup2(pv.z); fma2(o2[i][0], pd, vc.x); fma2(o2[i][1], pd, vc.y);
                pd = dup2(pv.w); fma2(o2[i][0], pd, vd.x); fma2(o2[i][1], pd, vd.y);
            }
        }
        __syncthreads();
    }

    // ---- epilogue: reduce l across the 16 tx lanes, write O, score ----
#pragma unroll
    for (int i = 0; i < 8; i++) {
        int q = q0 + ty * 8 + i;
        float lsum = l_i[i];
#pragma unroll
        for (int off = 8; off; off >>= 1)
            lsum += __shfl_xor_sync(0xffffffffu, lsum, off);
        float inv = 1.0f / lsum;
        float2 oa = unpack2(o2[i][0]);
        float2 ob = unpack2(o2[i][1]);
        *reinterpret_cast<float4*>(&g_attn[(size_t)(b * NTOK + q) * DINNER + h * DHE + tx * 4]) =
            make_float4(oa.x * inv, oa.y * inv, ob.x * inv, ob.y * inv);
        double ssum = scd[i];
#pragma unroll
        for (int off = 8; off; off >>= 1)
            ssum += __shfl_xor_sync(0xffffffffu, ssum, off);
        if (tx == 0) atomicAdd(&g_score[b * NTOK + q], ssum);
    }
}

// ---------------- sort + swap map --------------------------------------------
__global__ __launch_bounds__(1024) void sort_swap_kernel(const int* __restrict__ patches)
{
    int bb = blockIdx.x;
    int t = threadIdx.x;
    __shared__ double sval[NTOK];
    __shared__ int sidx[NTOK];
    sval[t] = g_score[bb * NTOK + t] / (double)g_nnz[t];
    sidx[t] = t;
    __syncthreads();

    for (int k = 2; k <= NTOK; k <<= 1) {
        for (int j = k >> 1; j > 0; j >>= 1) {
            int ixj = t ^ j;
            if (ixj > t) {
                double v1 = sval[t], v2 = sval[ixj];
                int i1 = sidx[t], i2 = sidx[ixj];
                bool gt = (v1 > v2) || (v1 == v2 && i1 > i2);
                bool up = ((t & k) == 0);
                if (gt == up) {
                    sval[t] = v2; sval[ixj] = v1;
                    sidx[t] = i2; sidx[ixj] = i1;
                }
            }
            __syncthreads();
        }
    }

    int bo = (BSZ - 1) - bb;
    g_src[bo * NTOK + t] = t;
    __syncthreads();
    if (t == 0) {
        int P = patches[0];
        for (int i = 1; i <= P; i++) {
            int ti = sidx[i];
            g_src[bo * NTOK + i] = ti;
            g_src[bo * NTOK + ti] = i;
        }
    }
}

// ---------------- GEMM 2: out = gather(attn) @ w_out + b_out -----------------
__global__ __launch_bounds__(256) void gemm_out_kernel(
    const float* __restrict__ Wo, const float* __restrict__ bias,
    float* __restrict__ Out)
{
    const int BM = 128, BN = 128, BK = 16;
    __shared__ float As[2][BK][BM + 8];
    __shared__ float Bs[2][BK][BN];
    __shared__ int rowmap[BM];
    int bm = blockIdx.y * BM;
    int bn = blockIdx.x * BN;
    int tid = threadIdx.x;
    int ty = tid >> 4, tx = tid & 15;

    if (tid < BM) {
        int row = bm + tid;
        rowmap[tid] = (row & ~(NTOK - 1)) + g_src[row];
    }
    __syncthreads();

    float4 pa[2], pb[2];
    int ar[2], ac4[2], br[2], bc4[2];
#pragma unroll
    for (int l = 0; l < 2; l++) {
        int idx = tid + l * 256;
        ar[l] = idx >> 2;  ac4[l] = idx & 3;
        br[l] = idx >> 5;  bc4[l] = idx & 31;
    }

    unsigned long long acc[8][4];
#pragma unroll
    for (int i = 0; i < 8; i++)
#pragma unroll
        for (int j = 0; j < 4; j++) acc[i][j] = 0ULL;

#pragma unroll
    for (int l = 0; l < 2; l++) {
        pa[l] = *reinterpret_cast<const float4*>(&g_attn[(size_t)rowmap[ar[l]] * DINNER + ac4[l] * 4]);
        pb[l] = *reinterpret_cast<const float4*>(&Wo[(size_t)br[l] * DMODEL + bn + bc4[l] * 4]);
    }
#pragma unroll
    for (int l = 0; l < 2; l++) {
        As[0][ac4[l] * 4 + 0][ar[l]] = pa[l].x;
        As[0][ac4[l] * 4 + 1][ar[l]] = pa[l].y;
        As[0][ac4[l] * 4 + 2][ar[l]] = pa[l].z;
        As[0][ac4[l] * 4 + 3][ar[l]] = pa[l].w;
        *reinterpret_cast<float4*>(&Bs[0][br[l]][bc4[l] * 4]) = pb[l];
    }
    __syncthreads();

    int buf = 0;
    for (int k0 = 0; k0 < DINNER; k0 += BK) {
        if (k0 + BK < DINNER) {
#pragma unroll
            for (int l = 0; l < 2; l++) {
                pa[l] = *reinterpret_cast<const float4*>(&g_attn[(size_t)rowmap[ar[l]] * DINNER + k0 + BK + ac4[l] * 4]);
                pb[l] = *reinterpret_cast<const float4*>(&Wo[(size_t)(k0 + BK + br[l]) * DMODEL + bn + bc4[l] * 4]);
            }
        }
#pragma unroll
        for (int k = 0; k < BK; k++) {
            float4 a0 = *reinterpret_cast<const float4*>(&As[buf][k][ty * 8]);
            float4 a1 = *reinterpret_cast<const float4*>(&As[buf][k][ty * 8 + 4]);
            ulonglong2 b01 = *reinterpret_cast<const ulonglong2*>(&Bs[buf][k][tx * 8]);
            ulonglong2 b23 = *reinterpret_cast<const ulonglong2*>(&Bs[buf][k][tx * 8 + 4]);
            float av[8] = {a0.x, a0.y, a0.z, a0.w, a1.x, a1.y, a1.z, a1.w};
#pragma unroll
            for (int i = 0; i < 8; i++) {
                unsigned long long ad = dup2(av[i]);
                fma2(acc[i][0], ad, b01.x);
                fma2(acc[i][1], ad, b01.y);
                fma2(acc[i][2], ad, b23.x);
                fma2(acc[i][3], ad, b23.y);
            }
        }
        if (k0 + BK < DINNER) {
            int nb = buf ^ 1;
#pragma unroll
            for (int l = 0; l < 2; l++) {
                As[nb][ac4[l] * 4 + 0][ar[l]] = pa[l].x;
                As[nb][ac4[l] * 4 + 1][ar[l]] = pa[l].y;
                As[nb][ac4[l] * 4 + 2][ar[l]] = pa[l].z;
                As[nb][ac4[l] * 4 + 3][ar[l]] = pa[l].w;
                *reinterpret_cast<float4*>(&Bs[nb][br[l]][bc4[l] * 4]) = pb[l];
            }
            __syncthreads();
            buf = nb;
        }
    }
#pragma unroll
    for (int i = 0; i < 8; i++) {
        int row = bm + ty * 8 + i;
        int col = bn + tx * 8;
        float2 c0 = unpack2(acc[i][0]), c1 = unpack2(acc[i][1]);
        float2 c2 = unpack2(acc[i][2]), c3 = unpack2(acc[i][3]);
        *reinterpret_cast<float4*>(&Out[(size_t)row * DMODEL + col]) =
            make_float4(c0.x + bias[col + 0], c0.y + bias[col + 1],
                        c1.x + bias[col + 2], c1.y + bias[col + 3]);
        *reinterpret_cast<float4*>(&Out[(size_t)row * DMODEL + col + 4]) =
            make_float4(c2.x + bias[col + 4], c2.y + bias[col + 5],
                        c3.x + bias[col + 6], c3.y + bias[col + 7]);
    }
}

// ---------------- launch ------------------------------------------------------
extern "C" void kernel_launch(void* const* d_in, const int* in_sizes, int n_in,
                              void* d_out, int out_size)
{
    const float* x       = (const float*)d_in[0];
    const int*   cp_mask = (const int*)d_in[1];
    const float* w_qkv   = (const float*)d_in[2];
    const float* w_out   = (const float*)d_in[3];
    const float* b_out   = (const float*)d_in[4];
    const int*   patches = (const int*)d_in[5];
    float* out = (float*)d_out;

    const int attn_smem = (64 * QTS + 64 * KTS + 128 * VTS + 128 * PTS) * (int)sizeof(float);
    cudaFuncSetAttribute(attn_kernel, cudaFuncAttributeMaxDynamicSharedMemorySize, attn_smem);

    zero_score_kernel<<<32, 256>>>();
    nnz_kernel<<<NTOK, 256>>>(cp_mask);
    gemm_qkv_kernel<<<dim3(QKV3 / 128, (BSZ * NTOK) / 128), 256>>>(x, w_qkv);
    attn_kernel<<<dim3(8, NH, BSZ), 256, attn_smem>>>(cp_mask);
    sort_swap_kernel<<<BSZ, 1024>>>(patches);
    gemm_out_kernel<<<dim3(DMODEL / 128, (BSZ * NTOK) / 128), 256>>>(w_out, b_out, out);
}